// round 1
// baseline (speedup 1.0000x reference)
#include <cuda_runtime.h>
#include <math.h>

#define TT 8192
#define DD 1024
#define HH 2752
#define NE 8
#define NJ 9          // 8 routed experts + 1 shared "expert"
#define NSLOT 3       // 2 routed slots + 1 shared slot

// ---------------- scratch (device globals; no allocation APIs) ----------------
static __device__ float g_act[(size_t)NJ * TT * HH];     // activation scratch per job row
static __device__ float g_ysc[(size_t)TT * NSLOT * DD];  // per (token, slot) outputs
static __device__ int   g_tok [NJ * TT];
static __device__ float g_wt  [NJ * TT];
static __device__ int   g_slot[NJ * TT];
static __device__ int   g_cnt [NJ];

// ---------------- init: reset counters, build shared-expert job ----------------
__global__ void init_k() {
    int i = blockIdx.x * blockDim.x + threadIdx.x;   // 0..TT-1
    if (i < NJ) g_cnt[i] = (i == NE) ? TT : 0;
    g_tok [NE * TT + i] = i;
    g_wt  [NE * TT + i] = 1.0f;
    g_slot[NE * TT + i] = 2;
}

// ---------------- gate + routing: warp per token ----------------
__global__ __launch_bounds__(256) void gate_route_k(const float* __restrict__ x,
                                                    const float* __restrict__ gw) {
    __shared__ float sg[NE * DD];
    int tid = threadIdx.x;
    for (int i = tid; i < NE * DD; i += 256) sg[i] = gw[i];
    __syncthreads();

    int warp = tid >> 5, lane = tid & 31;
    int t = blockIdx.x * 8 + warp;

    float acc[NE];
#pragma unroll
    for (int e = 0; e < NE; e++) acc[e] = 0.f;

    const float* xr = x + (size_t)t * DD;
    for (int k = lane; k < DD; k += 32) {
        float xv = xr[k];
#pragma unroll
        for (int e = 0; e < NE; e++) acc[e] += xv * sg[e * DD + k];
    }
#pragma unroll
    for (int e = 0; e < NE; e++) {
#pragma unroll
        for (int off = 16; off > 0; off >>= 1)
            acc[e] += __shfl_xor_sync(0xffffffffu, acc[e], off);
    }

    if (lane == 0) {
        float mx = acc[0];
#pragma unroll
        for (int e = 1; e < NE; e++) mx = fmaxf(mx, acc[e]);
        float p[NE];
#pragma unroll
        for (int e = 0; e < NE; e++) p[e] = expf(acc[e] - mx);
        // top-2 (first index wins ties, matching lax.top_k)
        int i1 = 0;
#pragma unroll
        for (int e = 1; e < NE; e++) if (p[e] > p[i1]) i1 = e;
        int i2 = (i1 == 0) ? 1 : 0;
#pragma unroll
        for (int e = 0; e < NE; e++) if (e != i1 && p[e] > p[i2]) i2 = e;
        float s = p[i1] + p[i2];
        float wA = p[i1] / s, wB = p[i2] / s;

        int pos = atomicAdd(&g_cnt[i1], 1);
        g_tok[i1 * TT + pos] = t;  g_wt[i1 * TT + pos] = wA;  g_slot[i1 * TT + pos] = 0;
        pos = atomicAdd(&g_cnt[i2], 1);
        g_tok[i2 * TT + pos] = t;  g_wt[i2 * TT + pos] = wB;  g_slot[i2 * TT + pos] = 1;
    }
}

// ---------------- GEMM1: act = silu(X@W1^T) * (X@W3^T), gathered rows ----------------
// 64x64 tile, BK=16, 256 threads, 4x4 microtile, dual accumulators.
__global__ __launch_bounds__(256) void gemm1_k(const float* __restrict__ x,
                                               const float* __restrict__ w1,
                                               const float* __restrict__ w3,
                                               const float* __restrict__ sw1,
                                               const float* __restrict__ sw3) {
    int j = blockIdx.z;
    int n = g_cnt[j];
    int row0 = blockIdx.y * 64;
    if (row0 >= n) return;
    int col0 = blockIdx.x * 64;

    const float* Wa, * Wb;
    if (j < NE) { Wa = w1 + (size_t)j * HH * DD; Wb = w3 + (size_t)j * HH * DD; }
    else        { Wa = sw1;                      Wb = sw3; }

    __shared__ float As[16][64];
    __shared__ float Ba[16][64];
    __shared__ float Bb[16][64];
    __shared__ int   stok[64];

    int tid = threadIdx.x;
    if (tid < 64) {
        int r = row0 + tid;
        stok[tid] = (r < n) ? g_tok[j * TT + r] : -1;
    }
    __syncthreads();

    int lr = tid >> 2;            // 0..63
    int lk = (tid & 3) << 2;      // 0,4,8,12
    int atok = stok[lr];
    const float* aptr  = (atok >= 0) ? x + (size_t)atok * DD + lk : nullptr;
    const float* bap   = Wa + (size_t)(col0 + lr) * DD + lk;
    const float* bbp   = Wb + (size_t)(col0 + lr) * DD + lk;

    int ty = tid >> 4, tx = tid & 15;

    float acc1[4][4], acc3[4][4];
#pragma unroll
    for (int i = 0; i < 4; i++)
#pragma unroll
        for (int c = 0; c < 4; c++) { acc1[i][c] = 0.f; acc3[i][c] = 0.f; }

    for (int k0 = 0; k0 < DD; k0 += 16) {
        float4 av = aptr ? *(const float4*)(aptr + k0) : make_float4(0.f, 0.f, 0.f, 0.f);
        float4 b1 = *(const float4*)(bap + k0);
        float4 b3 = *(const float4*)(bbp + k0);
        As[lk + 0][lr] = av.x; As[lk + 1][lr] = av.y; As[lk + 2][lr] = av.z; As[lk + 3][lr] = av.w;
        Ba[lk + 0][lr] = b1.x; Ba[lk + 1][lr] = b1.y; Ba[lk + 2][lr] = b1.z; Ba[lk + 3][lr] = b1.w;
        Bb[lk + 0][lr] = b3.x; Bb[lk + 1][lr] = b3.y; Bb[lk + 2][lr] = b3.z; Bb[lk + 3][lr] = b3.w;
        __syncthreads();
#pragma unroll
        for (int kk = 0; kk < 16; kk++) {
            float4 a = *(const float4*)&As[kk][ty * 4];
            float4 p = *(const float4*)&Ba[kk][tx * 4];
            float4 q = *(const float4*)&Bb[kk][tx * 4];
            float aa[4] = { a.x, a.y, a.z, a.w };
            float pp[4] = { p.x, p.y, p.z, p.w };
            float qq[4] = { q.x, q.y, q.z, q.w };
#pragma unroll
            for (int i = 0; i < 4; i++)
#pragma unroll
                for (int c = 0; c < 4; c++) {
                    acc1[i][c] += aa[i] * pp[c];
                    acc3[i][c] += aa[i] * qq[c];
                }
        }
        __syncthreads();
    }

#pragma unroll
    for (int i = 0; i < 4; i++) {
        int r = row0 + ty * 4 + i;
        if (r < n) {
            float v[4];
#pragma unroll
            for (int c = 0; c < 4; c++) {
                float h1 = acc1[i][c], h3 = acc3[i][c];
                v[c] = (h1 / (1.f + expf(-h1))) * h3;   // silu(h1)*h3
            }
            *(float4*)&g_act[((size_t)j * TT + r) * HH + col0 + tx * 4] =
                make_float4(v[0], v[1], v[2], v[3]);
        }
    }
}

// ---------------- GEMM2: y = act @ W2^T * weight, scattered to (token,slot) ----------------
__global__ __launch_bounds__(256) void gemm2_k(const float* __restrict__ w2,
                                               const float* __restrict__ sw2) {
    int j = blockIdx.z;
    int n = g_cnt[j];
    int row0 = blockIdx.y * 64;
    if (row0 >= n) return;
    int col0 = blockIdx.x * 64;

    const float* Wc = (j < NE) ? w2 + (size_t)j * DD * HH : sw2;

    __shared__ float As[16][64];
    __shared__ float Bs[16][64];
    __shared__ int   stok[64];
    __shared__ float swt[64];
    __shared__ int   sslot[64];

    int tid = threadIdx.x;
    if (tid < 64) {
        int r = row0 + tid;
        if (r < n) {
            stok [tid] = g_tok [j * TT + r];
            swt  [tid] = g_wt  [j * TT + r];
            sslot[tid] = g_slot[j * TT + r];
        } else {
            stok[tid] = -1; swt[tid] = 0.f; sslot[tid] = 0;
        }
    }
    __syncthreads();

    int lr = tid >> 2;
    int lk = (tid & 3) << 2;
    const float* aptr = g_act + ((size_t)j * TT + row0 + lr) * HH + lk;
    const float* bptr = Wc + (size_t)(col0 + lr) * HH + lk;

    int ty = tid >> 4, tx = tid & 15;

    float acc[4][4];
#pragma unroll
    for (int i = 0; i < 4; i++)
#pragma unroll
        for (int c = 0; c < 4; c++) acc[i][c] = 0.f;

    for (int k0 = 0; k0 < HH; k0 += 16) {
        float4 av = *(const float4*)(aptr + k0);
        float4 bv = *(const float4*)(bptr + k0);
        As[lk + 0][lr] = av.x; As[lk + 1][lr] = av.y; As[lk + 2][lr] = av.z; As[lk + 3][lr] = av.w;
        Bs[lk + 0][lr] = bv.x; Bs[lk + 1][lr] = bv.y; Bs[lk + 2][lr] = bv.z; Bs[lk + 3][lr] = bv.w;
        __syncthreads();
#pragma unroll
        for (int kk = 0; kk < 16; kk++) {
            float4 a = *(const float4*)&As[kk][ty * 4];
            float4 b = *(const float4*)&Bs[kk][tx * 4];
            float aa[4] = { a.x, a.y, a.z, a.w };
            float bb[4] = { b.x, b.y, b.z, b.w };
#pragma unroll
            for (int i = 0; i < 4; i++)
#pragma unroll
                for (int c = 0; c < 4; c++) acc[i][c] += aa[i] * bb[c];
        }
        __syncthreads();
    }

#pragma unroll
    for (int i = 0; i < 4; i++) {
        int rl = ty * 4 + i;
        int r = row0 + rl;
        if (r < n) {
            int   tk = stok[rl];
            float wg = swt[rl];
            int   sl = sslot[rl];
            float4 o = make_float4(acc[i][0] * wg, acc[i][1] * wg, acc[i][2] * wg, acc[i][3] * wg);
            *(float4*)&g_ysc[((size_t)tk * NSLOT + sl) * DD + col0 + tx * 4] = o;
        }
    }
}

// ---------------- combine: out = slot0 + slot1 + slot2 ----------------
__global__ void combine_k(float* __restrict__ out) {
    int idx = blockIdx.x * blockDim.x + threadIdx.x;  // over TT*DD/4
    int t  = idx >> 8;            // DD/4 = 256 float4 per token
    int d4 = (idx & 255) << 2;
    const float* b0 = g_ysc + ((size_t)t * NSLOT + 0) * DD + d4;
    const float* b1 = g_ysc + ((size_t)t * NSLOT + 1) * DD + d4;
    const float* b2 = g_ysc + ((size_t)t * NSLOT + 2) * DD + d4;
    float4 a = *(const float4*)b0;
    float4 b = *(const float4*)b1;
    float4 c = *(const float4*)b2;
    float4 o = make_float4(a.x + b.x + c.x, a.y + b.y + c.y,
                           a.z + b.z + c.z, a.w + b.w + c.w);
    *(float4*)(out + (size_t)t * DD + d4) = o;
}

// ---------------- launcher ----------------
extern "C" void kernel_launch(void* const* d_in, const int* in_sizes, int n_in,
                              void* d_out, int out_size) {
    const float* x   = (const float*)d_in[0];
    const float* gw  = (const float*)d_in[1];
    const float* w1  = (const float*)d_in[2];
    const float* w3  = (const float*)d_in[3];
    const float* w2  = (const float*)d_in[4];
    const float* sw1 = (const float*)d_in[5];
    const float* sw3 = (const float*)d_in[6];
    const float* sw2 = (const float*)d_in[7];
    float* out = (float*)d_out;

    init_k<<<TT / 256, 256>>>();
    gate_route_k<<<TT / 8, 256>>>(x, gw);
    gemm1_k<<<dim3(HH / 64, TT / 64, NJ), 256>>>(x, w1, w3, sw1, sw3);
    gemm2_k<<<dim3(DD / 64, TT / 64, NJ), 256>>>(w2, sw2);
    combine_k<<<(TT * DD / 4) / 256, 256>>>(out);
}

// round 7
// speedup vs baseline: 3.6289x; 3.6289x over previous
#include <cuda_runtime.h>
#include <cuda_bf16.h>
#include <math.h>
#include <stdint.h>

#define TT 8192
#define DD 1024
#define HH 2752
#define NE 8
#define NJ 9
#define NSLOT 3

#define SMEM_BYTES 65536   // 2 stages x 32KB

// ---------------- scratch (device globals) ----------------
static __device__ __nv_bfloat16 g_xgh[(size_t)NJ * TT * DD];
static __device__ __nv_bfloat16 g_xgl[(size_t)NJ * TT * DD];
static __device__ __nv_bfloat16 g_w1h[(size_t)NE * HH * DD];
static __device__ __nv_bfloat16 g_w1l[(size_t)NE * HH * DD];
static __device__ __nv_bfloat16 g_w3h[(size_t)NE * HH * DD];
static __device__ __nv_bfloat16 g_w3l[(size_t)NE * HH * DD];
static __device__ __nv_bfloat16 g_w2h[(size_t)NE * DD * HH];
static __device__ __nv_bfloat16 g_w2l[(size_t)NE * DD * HH];
static __device__ __nv_bfloat16 g_s1h[(size_t)HH * DD];
static __device__ __nv_bfloat16 g_s1l[(size_t)HH * DD];
static __device__ __nv_bfloat16 g_s3h[(size_t)HH * DD];
static __device__ __nv_bfloat16 g_s3l[(size_t)HH * DD];
static __device__ __nv_bfloat16 g_s2h[(size_t)DD * HH];
static __device__ __nv_bfloat16 g_s2l[(size_t)DD * HH];
static __device__ __nv_bfloat16 g_ah[(size_t)NJ * TT * HH];
static __device__ __nv_bfloat16 g_al[(size_t)NJ * TT * HH];
static __device__ float g_ysc[(size_t)TT * NSLOT * DD];
static __device__ int   g_tok [NJ * TT];
static __device__ float g_wt  [NJ * TT];
static __device__ int   g_slot[NJ * TT];
static __device__ int   g_cnt [NJ];

// ---------------- helpers ----------------
__device__ __forceinline__ uint32_t s2u(const void* p) {
    uint32_t a;
    asm("{ .reg .u64 t; cvta.to.shared.u64 t, %1; cvt.u32.u64 %0, t; }" : "=r"(a) : "l"(p));
    return a;
}
__device__ __forceinline__ uint32_t sw64(uint32_t o) { return o ^ ((o >> 3) & 0x30); }

__device__ __forceinline__ void cpa16(uint32_t dst, const void* src) {
    asm volatile("cp.async.cg.shared.global [%0], [%1], 16;" :: "r"(dst), "l"(src));
}
__device__ __forceinline__ void ldm_x4(uint32_t* r, uint32_t a) {
    asm volatile("ldmatrix.sync.aligned.m8n8.x4.shared.b16 {%0,%1,%2,%3}, [%4];"
                 : "=r"(r[0]), "=r"(r[1]), "=r"(r[2]), "=r"(r[3]) : "r"(a));
}
__device__ __forceinline__ void ldm_x2(uint32_t* r, uint32_t a) {
    asm volatile("ldmatrix.sync.aligned.m8n8.x2.shared.b16 {%0,%1}, [%2];"
                 : "=r"(r[0]), "=r"(r[1]) : "r"(a));
}
__device__ __forceinline__ void mma_bf16(float* c, const uint32_t* a, const uint32_t* b) {
    asm volatile("mma.sync.aligned.m16n8k16.row.col.f32.bf16.bf16.f32 "
                 "{%0,%1,%2,%3}, {%4,%5,%6,%7}, {%8,%9}, {%0,%1,%2,%3};"
                 : "+f"(c[0]), "+f"(c[1]), "+f"(c[2]), "+f"(c[3])
                 : "r"(a[0]), "r"(a[1]), "r"(a[2]), "r"(a[3]), "r"(b[0]), "r"(b[1]));
}

// ---------------- init ----------------
__global__ void init_k() {
    int i = blockIdx.x * blockDim.x + threadIdx.x;
    if (i < NJ) g_cnt[i] = (i == NE) ? TT : 0;
    g_tok [NE * TT + i] = i;
    g_wt  [NE * TT + i] = 1.0f;
    g_slot[NE * TT + i] = 2;
}

// ---------------- gate + routing ----------------
__global__ __launch_bounds__(256) void gate_route_k(const float* __restrict__ x,
                                                    const float* __restrict__ gw) {
    __shared__ float sg[NE * DD];
    int tid = threadIdx.x;
    for (int i = tid; i < NE * DD; i += 256) sg[i] = gw[i];
    __syncthreads();

    int warp = tid >> 5, lane = tid & 31;
    int t = blockIdx.x * 8 + warp;

    float acc[NE];
#pragma unroll
    for (int e = 0; e < NE; e++) acc[e] = 0.f;
    const float* xr = x + (size_t)t * DD;
    for (int k = lane; k < DD; k += 32) {
        float xv = xr[k];
#pragma unroll
        for (int e = 0; e < NE; e++) acc[e] += xv * sg[e * DD + k];
    }
#pragma unroll
    for (int e = 0; e < NE; e++) {
#pragma unroll
        for (int off = 16; off > 0; off >>= 1)
            acc[e] += __shfl_xor_sync(0xffffffffu, acc[e], off);
    }
    if (lane == 0) {
        float mx = acc[0];
#pragma unroll
        for (int e = 1; e < NE; e++) mx = fmaxf(mx, acc[e]);
        float p[NE];
#pragma unroll
        for (int e = 0; e < NE; e++) p[e] = expf(acc[e] - mx);
        int i1 = 0;
#pragma unroll
        for (int e = 1; e < NE; e++) if (p[e] > p[i1]) i1 = e;
        int i2 = (i1 == 0) ? 1 : 0;
#pragma unroll
        for (int e = 0; e < NE; e++) if (e != i1 && p[e] > p[i2]) i2 = e;
        float s = p[i1] + p[i2];
        float wA = p[i1] / s, wB = p[i2] / s;
        int pos = atomicAdd(&g_cnt[i1], 1);
        g_tok[i1 * TT + pos] = t;  g_wt[i1 * TT + pos] = wA;  g_slot[i1 * TT + pos] = 0;
        pos = atomicAdd(&g_cnt[i2], 1);
        g_tok[i2 * TT + pos] = t;  g_wt[i2 * TT + pos] = wB;  g_slot[i2 * TT + pos] = 1;
    }
}

// ---------------- weight fp32 -> bf16 hi/lo split ----------------
__global__ void convert_all_k(const float* __restrict__ w1, const float* __restrict__ w3,
                              const float* __restrict__ w2, const float* __restrict__ s1,
                              const float* __restrict__ s3, const float* __restrict__ s2) {
    int z = blockIdx.z;
    const float* in; __nv_bfloat16* hi; __nv_bfloat16* lo; size_t n;
    switch (z) {
        case 0: in = w1; hi = g_w1h; lo = g_w1l; n = (size_t)NE * HH * DD; break;
        case 1: in = w3; hi = g_w3h; lo = g_w3l; n = (size_t)NE * HH * DD; break;
        case 2: in = w2; hi = g_w2h; lo = g_w2l; n = (size_t)NE * DD * HH; break;
        case 3: in = s1; hi = g_s1h; lo = g_s1l; n = (size_t)HH * DD; break;
        case 4: in = s3; hi = g_s3h; lo = g_s3l; n = (size_t)DD * HH; break;
        default: in = s2; hi = g_s2h; lo = g_s2l; n = (size_t)DD * HH; break;
    }
    size_t i = (size_t)blockIdx.x * blockDim.x + threadIdx.x;
    size_t stride = (size_t)gridDim.x * blockDim.x;
    size_t n4 = n >> 2;
    for (; i < n4; i += stride) {
        float4 v = ((const float4*)in)[i];
        __nv_bfloat16 h0 = __float2bfloat16(v.x), h1 = __float2bfloat16(v.y);
        __nv_bfloat16 h2 = __float2bfloat16(v.z), h3 = __float2bfloat16(v.w);
        __nv_bfloat16 l0 = __float2bfloat16(v.x - __bfloat162float(h0));
        __nv_bfloat16 l1 = __float2bfloat16(v.y - __bfloat162float(h1));
        __nv_bfloat16 l2 = __float2bfloat16(v.z - __bfloat162float(h2));
        __nv_bfloat16 l3 = __float2bfloat16(v.w - __bfloat162float(h3));
        __nv_bfloat162 hp0; hp0.x = h0; hp0.y = h1;
        __nv_bfloat162 hp1; hp1.x = h2; hp1.y = h3;
        __nv_bfloat162 lp0; lp0.x = l0; lp0.y = l1;
        __nv_bfloat162 lp1; lp1.x = l2; lp1.y = l3;
        *(__nv_bfloat162*)&hi[i * 4 + 0] = hp0;
        *(__nv_bfloat162*)&hi[i * 4 + 2] = hp1;
        *(__nv_bfloat162*)&lo[i * 4 + 0] = lp0;
        *(__nv_bfloat162*)&lo[i * 4 + 2] = lp1;
    }
}

// ---------------- gather routed tokens, split to hi/lo ----------------
__global__ __launch_bounds__(128) void gather_k(const float* __restrict__ x) {
    int j = blockIdx.y, i = blockIdx.x;
    if (i >= g_cnt[j]) return;
    int tok = g_tok[j * TT + i];
    const float4* src = (const float4*)(x + (size_t)tok * DD);
    size_t dst = ((size_t)j * TT + i) * DD;
    for (int c = threadIdx.x; c < DD / 4; c += 128) {
        float4 v = src[c];
        __nv_bfloat16 h0 = __float2bfloat16(v.x), h1 = __float2bfloat16(v.y);
        __nv_bfloat16 h2 = __float2bfloat16(v.z), h3 = __float2bfloat16(v.w);
        __nv_bfloat16 l0 = __float2bfloat16(v.x - __bfloat162float(h0));
        __nv_bfloat16 l1 = __float2bfloat16(v.y - __bfloat162float(h1));
        __nv_bfloat16 l2 = __float2bfloat16(v.z - __bfloat162float(h2));
        __nv_bfloat16 l3 = __float2bfloat16(v.w - __bfloat162float(h3));
        __nv_bfloat162 hp0; hp0.x = h0; hp0.y = h1;
        __nv_bfloat162 hp1; hp1.x = h2; hp1.y = h3;
        __nv_bfloat162 lp0; lp0.x = l0; lp0.y = l1;
        __nv_bfloat162 lp1; lp1.x = l2; lp1.y = l3;
        *(__nv_bfloat162*)&g_xgh[dst + c * 4 + 0] = hp0;
        *(__nv_bfloat162*)&g_xgh[dst + c * 4 + 2] = hp1;
        *(__nv_bfloat162*)&g_xgl[dst + c * 4 + 0] = lp0;
        *(__nv_bfloat162*)&g_xgl[dst + c * 4 + 2] = lp1;
    }
}

// ================= GEMM1: act = silu(X@W1^T) * (X@W3^T) =================
// BM=128, BN=64 per matrix (w1 & w3 together), BK=32, 8 warps (4Mx2N),
// warp tile 32x32 per matrix, bf16x2 3-pass via mma.sync m16n8k16.
// Stage layout (32KB): A_hi 0, A_lo 8K, B1h 16K, B1l 20K, B3h 24K, B3l 28K.
__global__ __launch_bounds__(256) void gemm1_k() {
    int j = blockIdx.z;
    int n = g_cnt[j];
    int row0 = blockIdx.y * 128;
    if (row0 >= n) return;
    int col0 = blockIdx.x * 64;

    extern __shared__ __align__(1024) char smem[];
    uint32_t sb = s2u(smem);
    int tid = threadIdx.x;
    int wid = tid >> 5, lane = tid & 31;
    int wm = wid >> 1, wn = wid & 1;

    const __nv_bfloat16 *w1h, *w1l, *w3h, *w3l;
    if (j < NE) {
        size_t o = (size_t)j * HH * DD;
        w1h = g_w1h + o; w1l = g_w1l + o; w3h = g_w3h + o; w3l = g_w3l + o;
    } else { w1h = g_s1h; w1l = g_s1l; w3h = g_s3h; w3l = g_s3l; }
    const __nv_bfloat16* xh = g_xgh + ((size_t)j * TT + row0) * DD;
    const __nv_bfloat16* xl = g_xgl + ((size_t)j * TT + row0) * DD;

    float acc1[2][4][4], acc3[2][4][4];
#pragma unroll
    for (int mt = 0; mt < 2; mt++)
#pragma unroll
        for (int nt = 0; nt < 4; nt++)
#pragma unroll
            for (int e = 0; e < 4; e++) { acc1[mt][nt][e] = 0.f; acc3[mt][nt][e] = 0.f; }

    const int NCH = DD / 32;   // 32

    // ---- stage loader ----
    auto load_stage = [&](int ch) {
        uint32_t st = sb + (ch & 1) * 32768;
        int k0 = ch * 32;
#pragma unroll
        for (int u = tid; u < 512; u += 256) {
            int r = u >> 2, c = u & 3;
            uint32_t d = st + sw64((uint32_t)(r * 64 + c * 16));
            size_t so = (size_t)r * DD + k0 + c * 8;
            cpa16(d, xh + so);
            cpa16(d + 8192, xl + so);
        }
        {
            int u = tid;  // 256 entries: 64 rows x 4 chunks
            int r = u >> 2, c = u & 3;
            uint32_t d = st + 16384 + sw64((uint32_t)(r * 64 + c * 16));
            size_t so = (size_t)(col0 + r) * DD + k0 + c * 8;
            cpa16(d, w1h + so);
            cpa16(d + 4096, w1l + so);
            cpa16(d + 8192, w3h + so);
            cpa16(d + 12288, w3l + so);
        }
        asm volatile("cp.async.commit_group;");
    };

    load_stage(0);
    for (int ch = 0; ch < NCH; ch++) {
        if (ch + 1 < NCH) {
            load_stage(ch + 1);
            asm volatile("cp.async.wait_group 1;" ::: "memory");
        } else {
            asm volatile("cp.async.wait_group 0;" ::: "memory");
        }
        __syncthreads();

        uint32_t st = sb + (ch & 1) * 32768;
#pragma unroll
        for (int ks = 0; ks < 2; ks++) {
            int kk = ks * 16;
            // A fragments (hi & lo), 2 m-tiles
            uint32_t ah[2][4], al[2][4];
#pragma unroll
            for (int mt = 0; mt < 2; mt++) {
                uint32_t byte = (uint32_t)((wm * 32 + mt * 16 + (lane & 15)) * 64
                                           + kk * 2 + (lane >> 4) * 16);
                uint32_t swb = sw64(byte);
                ldm_x4(ah[mt], st + swb);
                ldm_x4(al[mt], st + 8192 + swb);
            }
            uint32_t bbyte = (uint32_t)((wn * 32 + (lane & 7)) * 64
                                        + kk * 2 + ((lane >> 3) & 1) * 16);
            // ---- w1 ----
            {
                uint32_t bh[4][2], bl[4][2];
#pragma unroll
                for (int nt = 0; nt < 4; nt++) {
                    uint32_t swb = sw64(bbyte + nt * 8 * 64);
                    ldm_x2(bh[nt], st + 16384 + swb);
                    ldm_x2(bl[nt], st + 20480 + swb);
                }
#pragma unroll
                for (int mt = 0; mt < 2; mt++)
#pragma unroll
                    for (int nt = 0; nt < 4; nt++) {
                        mma_bf16(acc1[mt][nt], ah[mt], bh[nt]);
                        mma_bf16(acc1[mt][nt], ah[mt], bl[nt]);
                        mma_bf16(acc1[mt][nt], al[mt], bh[nt]);
                    }
            }
            // ---- w3 ----
            {
                uint32_t bh[4][2], bl[4][2];
#pragma unroll
                for (int nt = 0; nt < 4; nt++) {
                    uint32_t swb = sw64(bbyte + nt * 8 * 64);
                    ldm_x2(bh[nt], st + 24576 + swb);
                    ldm_x2(bl[nt], st + 28672 + swb);
                }
#pragma unroll
                for (int mt = 0; mt < 2; mt++)
#pragma unroll
                    for (int nt = 0; nt < 4; nt++) {
                        mma_bf16(acc3[mt][nt], ah[mt], bh[nt]);
                        mma_bf16(acc3[mt][nt], ah[mt], bl[nt]);
                        mma_bf16(acc3[mt][nt], al[mt], bh[nt]);
                    }
            }
        }
        __syncthreads();
    }

    // ---- epilogue: silu(h1)*h3 -> bf16 hi/lo ----
#pragma unroll
    for (int mt = 0; mt < 2; mt++) {
#pragma unroll
        for (int half = 0; half < 2; half++) {
            int r = row0 + wm * 32 + mt * 16 + (lane >> 2) + half * 8;
            if (r < n) {
                size_t rowbase = ((size_t)j * TT + r) * HH;
#pragma unroll
                for (int nt = 0; nt < 4; nt++) {
                    int col = col0 + wn * 32 + nt * 8 + 2 * (lane & 3);
                    float a0 = acc1[mt][nt][half * 2 + 0];
                    float a1 = acc1[mt][nt][half * 2 + 1];
                    float b0 = acc3[mt][nt][half * 2 + 0];
                    float b1 = acc3[mt][nt][half * 2 + 1];
                    float v0 = a0 / (1.f + __expf(-a0)) * b0;
                    float v1 = a1 / (1.f + __expf(-a1)) * b1;
                    __nv_bfloat16 h0 = __float2bfloat16(v0), h1 = __float2bfloat16(v1);
                    __nv_bfloat16 l0 = __float2bfloat16(v0 - __bfloat162float(h0));
                    __nv_bfloat16 l1 = __float2bfloat16(v1 - __bfloat162float(h1));
                    __nv_bfloat162 hp; hp.x = h0; hp.y = h1;
                    __nv_bfloat162 lp; lp.x = l0; lp.y = l1;
                    *(__nv_bfloat162*)&g_ah[rowbase + col] = hp;
                    *(__nv_bfloat162*)&g_al[rowbase + col] = lp;
                }
            }
        }
    }
}

// ================= GEMM2: y = (act @ W2^T) * wt -> scatter =================
// BM=128, BN=128, BK=32, warp tile 32x64.
// Stage layout (32KB): A_hi 0, A_lo 8K, B_h 16K, B_l 24K.
__global__ __launch_bounds__(256) void gemm2_k() {
    int j = blockIdx.z;
    int n = g_cnt[j];
    int row0 = blockIdx.y * 128;
    if (row0 >= n) return;
    int col0 = blockIdx.x * 128;

    extern __shared__ __align__(1024) char smem[];
    uint32_t sb = s2u(smem);
    int tid = threadIdx.x;
    int wid = tid >> 5, lane = tid & 31;
    int wm = wid >> 1, wn = wid & 1;

    const __nv_bfloat16 *w2h, *w2l;
    if (j < NE) { size_t o = (size_t)j * DD * HH; w2h = g_w2h + o; w2l = g_w2l + o; }
    else        { w2h = g_s2h; w2l = g_s2l; }
    const __nv_bfloat16* ahp = g_ah + ((size_t)j * TT + row0) * HH;
    const __nv_bfloat16* alp = g_al + ((size_t)j * TT + row0) * HH;

    float acc[2][8][4];
#pragma unroll
    for (int mt = 0; mt < 2; mt++)
#pragma unroll
        for (int nt = 0; nt < 8; nt++)
#pragma unroll
            for (int e = 0; e < 4; e++) acc[mt][nt][e] = 0.f;

    const int NCH = HH / 32;   // 86

    auto load_stage = [&](int ch) {
        uint32_t st = sb + (ch & 1) * 32768;
        int k0 = ch * 32;
#pragma unroll
        for (int u = tid; u < 512; u += 256) {
            int r = u >> 2, c = u & 3;
            uint32_t swb = sw64((uint32_t)(r * 64 + c * 16));
            size_t sa = (size_t)r * HH + k0 + c * 8;
            cpa16(st + swb, ahp + sa);
            cpa16(st + 8192 + swb, alp + sa);
            size_t sv = (size_t)(col0 + r) * HH + k0 + c * 8;
            cpa16(st + 16384 + swb, w2h + sv);
            cpa16(st + 24576 + swb, w2l + sv);
        }
        asm volatile("cp.async.commit_group;");
    };

    load_stage(0);
    for (int ch = 0; ch < NCH; ch++) {
        if (ch + 1 < NCH) {
            load_stage(ch + 1);
            asm volatile("cp.async.wait_group 1;" ::: "memory");
        } else {
            asm volatile("cp.async.wait_group 0;" ::: "memory");
        }
        __syncthreads();

        uint32_t st = sb + (ch & 1) * 32768;
#pragma unroll
        for (int ks = 0; ks < 2; ks++) {
            int kk = ks * 16;
            uint32_t ah[2][4], al[2][4];
#pragma unroll
            for (int mt = 0; mt < 2; mt++) {
                uint32_t byte = (uint32_t)((wm * 32 + mt * 16 + (lane & 15)) * 64
                                           + kk * 2 + (lane >> 4) * 16);
                uint32_t swb = sw64(byte);
                ldm_x4(ah[mt], st + swb);
                ldm_x4(al[mt], st + 8192 + swb);
            }
            uint32_t bbyte = (uint32_t)((wn * 64 + (lane & 7)) * 64
                                        + kk * 2 + ((lane >> 3) & 1) * 16);
#pragma unroll
            for (int g = 0; g < 2; g++) {     // n-tile groups 0-3, 4-7
                uint32_t bh[4][2], bl[4][2];
#pragma unroll
                for (int q = 0; q < 4; q++) {
                    uint32_t swb = sw64(bbyte + (g * 4 + q) * 8 * 64);
                    ldm_x2(bh[q], st + 16384 + swb);
                    ldm_x2(bl[q], st + 24576 + swb);
                }
#pragma unroll
                for (int mt = 0; mt < 2; mt++)
#pragma unroll
                    for (int q = 0; q < 4; q++) {
                        mma_bf16(acc[mt][g * 4 + q], ah[mt], bh[q]);
                        mma_bf16(acc[mt][g * 4 + q], ah[mt], bl[q]);
                        mma_bf16(acc[mt][g * 4 + q], al[mt], bh[q]);
                    }
            }
        }
        __syncthreads();
    }

    // ---- epilogue: weighted scatter ----
#pragma unroll
    for (int mt = 0; mt < 2; mt++) {
#pragma unroll
        for (int half = 0; half < 2; half++) {
            int r = row0 + wm * 32 + mt * 16 + (lane >> 2) + half * 8;
            if (r < n) {
                int   tok = g_tok [j * TT + r];
                float wt  = g_wt  [j * TT + r];
                int   sl  = g_slot[j * TT + r];
                float* yb = g_ysc + ((size_t)tok * NSLOT + sl) * DD;
#pragma unroll
                for (int nt = 0; nt < 8; nt++) {
                    int col = col0 + wn * 64 + nt * 8 + 2 * (lane & 3);
                    float2 o;
                    o.x = acc[mt][nt][half * 2 + 0] * wt;
                    o.y = acc[mt][nt][half * 2 + 1] * wt;
                    *(float2*)&yb[col] = o;
                }
            }
        }
    }
}

// ---------------- combine ----------------
__global__ void combine_k(float* __restrict__ out) {
    int idx = blockIdx.x * blockDim.x + threadIdx.x;
    int t = idx >> 8;
    int d4 = (idx & 255) << 2;
    const float* b0 = g_ysc + ((size_t)t * NSLOT + 0) * DD + d4;
    const float* b1 = g_ysc + ((size_t)t * NSLOT + 1) * DD + d4;
    const float* b2 = g_ysc + ((size_t)t * NSLOT + 2) * DD + d4;
    float4 a = *(const float4*)b0;
    float4 b = *(const float4*)b1;
    float4 c = *(const float4*)b2;
    float4 o = make_float4(a.x + b.x + c.x, a.y + b.y + c.y,
                           a.z + b.z + c.z, a.w + b.w + c.w);
    *(float4*)(out + (size_t)t * DD + d4) = o;
}

// ---------------- launcher ----------------
extern "C" void kernel_launch(void* const* d_in, const int* in_sizes, int n_in,
                              void* d_out, int out_size) {
    const float* x   = (const float*)d_in[0];
    const float* gw  = (const float*)d_in[1];
    const float* w1  = (const float*)d_in[2];
    const float* w3  = (const float*)d_in[3];
    const float* w2  = (const float*)d_in[4];
    const float* sw1 = (const float*)d_in[5];
    const float* sw3 = (const float*)d_in[6];
    const float* sw2 = (const float*)d_in[7];
    float* out = (float*)d_out;

    static int attr_done = 0;
    if (!attr_done) {
        cudaFuncSetAttribute(gemm1_k, cudaFuncAttributeMaxDynamicSharedMemorySize, SMEM_BYTES);
        cudaFuncSetAttribute(gemm2_k, cudaFuncAttributeMaxDynamicSharedMemorySize, SMEM_BYTES);
        attr_done = 1;
    }

    init_k<<<TT / 256, 256>>>();
    gate_route_k<<<TT / 8, 256>>>(x, gw);
    convert_all_k<<<dim3(4096, 1, 6), 256>>>(w1, w3, w2, sw1, sw3, sw2);
    gather_k<<<dim3(TT, NJ), 128>>>(x);
    gemm1_k<<<dim3(HH / 64, TT / 128, NJ), 256, SMEM_BYTES>>>();
    gemm2_k<<<dim3(DD / 128, TT / 128, NJ), 256, SMEM_BYTES>>>();
    combine_k<<<(TT * DD / 4) / 256, 256>>>(out);
}